// round 14
// baseline (speedup 1.0000x reference)
#include <cuda_runtime.h>
#include <cstdint>
#include <cstddef>

// Problem constants
#define BATCH   1024
#define SEQ     512
#define NFEAT   64
#define HID     128
#define GATES   512          // 4*HID
#define NOUT    128

// LSTM persistent kernel config
#define NCTA    128
#define BR      8            // batch rows per CTA
#define LTHREADS 512
#define SMEM_K4 27           // k4 blocks of W_hh in smem (27*8KB = 216 KB)
#define STR_K4  5            // k4 blocks streamed from L2 each step
#define HSTRIDE 132          // padded h row stride (floats): banks shift 4/row, 16B-aligned

// Scratch (device globals; no allocations allowed)
__device__ float  g_xg[(size_t)BATCH * SEQ * GATES];   // x@W_ih^T + b_ih + b_hh, [bt][gate]
__device__ float4 g_Wq[32 * GATES];                    // W_hh repacked: [k4][row] = W_hh[row][4k4..4k4+3]

// ---------------------------------------------------------------------------
__device__ __forceinline__ void ffma2(unsigned long long& d,
                                      unsigned long long a,
                                      unsigned long long b) {
    asm("fma.rn.f32x2 %0, %1, %2, %0;" : "+l"(d) : "l"(a), "l"(b));
}

__device__ __forceinline__ float hsum2(unsigned long long v) {
    float lo = __int_as_float((unsigned int)(v & 0xffffffffULL));
    float hi = __int_as_float((unsigned int)(v >> 32));
    return lo + hi;
}

__device__ __forceinline__ float sigmoid_f(float x) {
    return __fdividef(1.0f, 1.0f + __expf(-x));
}
__device__ __forceinline__ float tanh_f(float x) {
    return 1.0f - __fdividef(2.0f, __expf(2.0f * x) + 1.0f);
}

// ---------------------------------------------------------------------------
// Kernel 1: xg[bt][n] = sum_f x[bt][f] * W_ih[n][f] + b_ih[n] + b_hh[n]
// Block (0,0) additionally repacks W_hh into g_Wq (consumed by the NEXT kernel).
// ---------------------------------------------------------------------------
__global__ __launch_bounds__(256) void xg_kernel(const float* __restrict__ x,
                                                 const float* __restrict__ Wih,
                                                 const float* __restrict__ Whh,
                                                 const float* __restrict__ b_ih,
                                                 const float* __restrict__ b_hh) {
    __shared__ float As[64][66];
    __shared__ float Bs[64][66];

    const int bt0 = blockIdx.x * 64;
    const int n0  = blockIdx.y * 64;
    const int tid = threadIdx.x;

    if (blockIdx.x == 0 && blockIdx.y == 0) {
#pragma unroll
        for (int p = 0; p < 2; p++) {
            int row = tid + p * 256;
            const float4* src = (const float4*)(Whh + (size_t)row * HID);
#pragma unroll
            for (int k4 = 0; k4 < 32; k4++)
                g_Wq[k4 * GATES + row] = src[k4];
        }
    }

    const float4* Ag = (const float4*)(x   + (size_t)bt0 * NFEAT);
    const float4* Bg = (const float4*)(Wih + (size_t)n0  * NFEAT);
#pragma unroll
    for (int p = 0; p < 4; p++) {
        int v = tid + p * 256;
        int m = v >> 4;
        int k = (v & 15) * 4;
        float4 qa = Ag[v];
        As[m][k] = qa.x; As[m][k+1] = qa.y; As[m][k+2] = qa.z; As[m][k+3] = qa.w;
        float4 qb = Bg[v];
        Bs[m][k] = qb.x; Bs[m][k+1] = qb.y; Bs[m][k+2] = qb.z; Bs[m][k+3] = qb.w;
    }
    __syncthreads();

    const int tx = tid & 31;
    const int ty = tid >> 5;

    unsigned long long acc[8][2];
#pragma unroll
    for (int i = 0; i < 8; i++)
#pragma unroll
        for (int j = 0; j < 2; j++) acc[i][j] = 0ULL;

#pragma unroll
    for (int k2 = 0; k2 < 32; k2++) {
        unsigned long long a2[8], b2[2];
#pragma unroll
        for (int i = 0; i < 8; i++)
            a2[i] = *(const unsigned long long*)&As[ty + i * 8][k2 * 2];
#pragma unroll
        for (int j = 0; j < 2; j++)
            b2[j] = *(const unsigned long long*)&Bs[tx + j * 32][k2 * 2];
#pragma unroll
        for (int i = 0; i < 8; i++)
#pragma unroll
            for (int j = 0; j < 2; j++)
                ffma2(acc[i][j], a2[i], b2[j]);
    }

    float bias[2];
#pragma unroll
    for (int j = 0; j < 2; j++) {
        int n = n0 + tx + j * 32;
        bias[j] = __ldg(&b_ih[n]) + __ldg(&b_hh[n]);
    }

#pragma unroll
    for (int i = 0; i < 8; i++) {
        int m = bt0 + ty + i * 8;
#pragma unroll
        for (int j = 0; j < 2; j++) {
            int n = n0 + tx + j * 32;
            g_xg[(size_t)m * GATES + n] = hsum2(acc[i][j]) + bias[j];
        }
    }
}

// ---------------------------------------------------------------------------
// Kernel 2: persistent LSTM, fused 2-row x 4-gate cells, coalesced warp tiling.
// Warp = 4 row-pairs x 8 consecutive j. Thread (rg, j) owns outputs (2rg, j)
// and (2rg+1, j): all 4 gate dots + nonlinearity + state update in-thread.
//   h LDS: 4 distinct rows/warp-load (64B/wf, padded stride = conflict-free)
//   w LDS: 8 consecutive 16B/warp-load (128B/wf, full crossbar)
// Weights k4 0..26 in smem; k4 27..31 streamed from L2 via depth-3 rolling
// register prefetch. ONE barrier per step; h double-buffered.
// ---------------------------------------------------------------------------
extern __shared__ char smem_raw[];

__global__ __launch_bounds__(LTHREADS, 1) void lstm_kernel(
        const float* __restrict__ W_out,
        const float* __restrict__ b_out,
        float* __restrict__ out) {

    // smem carve: weights (27*8192 = 221184B) | h double buffer (2*8*132*4 = 8448B)
    ulonglong2* w4s = (ulonglong2*)smem_raw;                        // [SMEM_K4][512]
    float* hbuf = (float*)(smem_raw + SMEM_K4 * GATES * 16);        // [2][8][HSTRIDE]

    const int tid  = threadIdx.x;
    const int b0   = blockIdx.x * BR;
    const int lane = tid & 31;
    const int warp = tid >> 5;
    const int rg   = lane >> 3;            // row-pair 0..3 -> rows 2rg, 2rg+1
    const int j    = warp * 8 + (lane & 7);  // output/hidden index 0..127

    const ulonglong2* __restrict__ Wg = (const ulonglong2*)g_Wq;

    // Prologue: smem weights (k4 0..26), zero h buffers
#pragma unroll
    for (int p = 0; p < SMEM_K4; p++) {
        int idx = tid + p * LTHREADS;
        w4s[idx] = Wg[idx];
    }
    for (int i = tid; i < 2 * BR * HSTRIDE; i += LTHREADS) hbuf[i] = 0.0f;
    __syncthreads();

    float cst[2] = {0.0f, 0.0f};

    for (int t = 0; t < SEQ; t++) {
        const int rb = t & 1;
        const float* __restrict__ hr = hbuf + rb * (BR * HSTRIDE);
        float*       __restrict__ hw = hbuf + (rb ^ 1) * (BR * HSTRIDE);

        // -- Prefetch (independent of h): first 3 streamed weight blocks + xg --
        ulonglong2 wpre[3][4];
#pragma unroll
        for (int s = 0; s < 3; s++)
#pragma unroll
            for (int g = 0; g < 4; g++)
                wpre[s][g] = Wg[(size_t)(SMEM_K4 + s) * GATES + g * HID + j];

        float xg_v[2][4];
#pragma unroll
        for (int p = 0; p < 2; p++) {
            size_t base = ((size_t)((b0 + 2 * rg + p) * SEQ + t)) * GATES + j;
#pragma unroll
            for (int g = 0; g < 4; g++)
                xg_v[p][g] = __ldg(&g_xg[base + g * HID]);
        }

        unsigned long long acc[2][4];
#pragma unroll
        for (int p = 0; p < 2; p++)
#pragma unroll
            for (int g = 0; g < 4; g++) acc[p][g] = 0ULL;

        // -- smem weight section: k4 0..26 --
#pragma unroll 9
        for (int k4 = 0; k4 < SMEM_K4; k4++) {
            ulonglong2 h0 = *(const ulonglong2*)&hr[(2 * rg)     * HSTRIDE + k4 * 4];
            ulonglong2 h1 = *(const ulonglong2*)&hr[(2 * rg + 1) * HSTRIDE + k4 * 4];
#pragma unroll
            for (int g = 0; g < 4; g++) {
                ulonglong2 w = w4s[k4 * GATES + g * HID + j];
                ffma2(acc[0][g], h0.x, w.x);
                ffma2(acc[0][g], h0.y, w.y);
                ffma2(acc[1][g], h1.x, w.x);
                ffma2(acc[1][g], h1.y, w.y);
            }
        }

        // -- streamed weight section: k4 27..31, rolling depth-3 prefetch --
#pragma unroll
        for (int s = 0; s < STR_K4; s++) {
            int k4 = SMEM_K4 + s;
            ulonglong2 wc[4];
#pragma unroll
            for (int g = 0; g < 4; g++) wc[g] = wpre[s % 3][g];
            if (s < STR_K4 - 3) {
#pragma unroll
                for (int g = 0; g < 4; g++)
                    wpre[s % 3][g] = Wg[(size_t)(SMEM_K4 + s + 3) * GATES + g * HID + j];
            }
            ulonglong2 h0 = *(const ulonglong2*)&hr[(2 * rg)     * HSTRIDE + k4 * 4];
            ulonglong2 h1 = *(const ulonglong2*)&hr[(2 * rg + 1) * HSTRIDE + k4 * 4];
#pragma unroll
            for (int g = 0; g < 4; g++) {
                ffma2(acc[0][g], h0.x, wc[g].x);
                ffma2(acc[0][g], h0.y, wc[g].y);
                ffma2(acc[1][g], h1.x, wc[g].x);
                ffma2(acc[1][g], h1.y, wc[g].y);
            }
        }

        // -- Fused nonlinearity + state update (same thread owns all 4 gates) --
#pragma unroll
        for (int p = 0; p < 2; p++) {
            float gi = hsum2(acc[p][0]) + xg_v[p][0];
            float gf = hsum2(acc[p][1]) + xg_v[p][1];
            float gg = hsum2(acc[p][2]) + xg_v[p][2];
            float go = hsum2(acc[p][3]) + xg_v[p][3];
            float iv = sigmoid_f(gi);
            float fv = sigmoid_f(gf);
            float gv = tanh_f(gg);
            float ov = sigmoid_f(go);
            float cc = fv * cst[p] + iv * gv;
            cst[p] = cc;
            hw[(2 * rg + p) * HSTRIDE + j] = ov * tanh_f(cc);
        }
        __syncthreads();   // single barrier: writes to hw visible; hr free to overwrite
    }

    // Final h: t=511 wrote buffer 0
    const float* hf = hbuf;   // [8][HSTRIDE]

    // -- Output projection: out[b][o] = h[b] . W_out[o] + b_out[o] --
#pragma unroll
    for (int p = 0; p < 2; p++) {
        int idx = tid + p * LTHREADS;      // 0..1023 -> (r, o)
        int r = idx >> 7;
        int o = idx & 127;
        const float4* wo  = (const float4*)(W_out + (size_t)o * HID);
        const float4* hrr = (const float4*)&hf[r * HSTRIDE];
        float s = __ldg(&b_out[o]);
#pragma unroll
        for (int k4 = 0; k4 < 32; k4++) {
            float4 w = wo[k4];
            float4 h = hrr[k4];
            s += w.x * h.x + w.y * h.y + w.z * h.z + w.w * h.w;
        }
        out[(size_t)(b0 + r) * NOUT + o] = s;
    }
}

// ---------------------------------------------------------------------------
// Launch (2 kernels)
// ---------------------------------------------------------------------------
extern "C" void kernel_launch(void* const* d_in, const int* in_sizes, int n_in,
                              void* d_out, int out_size) {
    const float* x     = (const float*)d_in[0];
    const float* W_ih  = (const float*)d_in[1];
    const float* W_hh  = (const float*)d_in[2];
    const float* b_ih  = (const float*)d_in[3];
    const float* b_hh  = (const float*)d_in[4];
    const float* W_out = (const float*)d_in[5];
    const float* b_out = (const float*)d_in[6];
    float* out = (float*)d_out;

    const int lstm_smem = SMEM_K4 * GATES * 16 + 2 * BR * HSTRIDE * 4; // 221184 + 8448
    cudaFuncSetAttribute(lstm_kernel,
                         cudaFuncAttributeMaxDynamicSharedMemorySize, lstm_smem);

    dim3 grid1((BATCH * SEQ) / 64, GATES / 64);
    xg_kernel<<<grid1, 256>>>(x, W_ih, W_hh, b_ih, b_hh);

    lstm_kernel<<<NCTA, LTHREADS, lstm_smem>>>(W_out, b_out, out);
}

// round 15
// speedup vs baseline: 1.0672x; 1.0672x over previous
#include <cuda_runtime.h>
#include <cstdint>
#include <cstddef>

// Problem constants
#define BATCH   1024
#define SEQ     512
#define NFEAT   64
#define HID     128
#define GATES   512          // 4*HID
#define NOUT    128

// LSTM persistent kernel config
#define NCTA    128
#define BR      8            // batch rows per CTA
#define LTHREADS 512
#define SMEM_K4 27           // k4 blocks of W_hh in smem (27*8KB = 216 KB)
#define STR_K4  5            // k4 blocks streamed from L2 each step (no reg residency)
#define HSTRIDE 132          // padded h row stride (floats): conflict-free 4-row access

// Scratch (device globals; no allocations allowed)
__device__ float  g_xg[(size_t)BATCH * SEQ * GATES];   // x@W_ih^T + b_ih + b_hh, [bt][gate]
__device__ float4 g_Wq[32 * GATES];                    // W_hh repacked: [k4][row] = W_hh[row][4k4..4k4+3]

// ---------------------------------------------------------------------------
__device__ __forceinline__ void ffma2(unsigned long long& d,
                                      unsigned long long a,
                                      unsigned long long b) {
    asm("fma.rn.f32x2 %0, %1, %2, %0;" : "+l"(d) : "l"(a), "l"(b));
}

__device__ __forceinline__ float hsum2(unsigned long long v) {
    float lo = __int_as_float((unsigned int)(v & 0xffffffffULL));
    float hi = __int_as_float((unsigned int)(v >> 32));
    return lo + hi;
}

// Volatile 16B global load: prevents ptxas from hoisting loop-invariant
// weight loads into persistent registers (the R12/R14 spill trigger).
__device__ __forceinline__ ulonglong2 ldg_w(const ulonglong2* p) {
    ulonglong2 r;
    asm volatile("ld.global.nc.v2.u64 {%0,%1}, [%2];"
                 : "=l"(r.x), "=l"(r.y) : "l"(p));
    return r;
}

// HW tanh approx (MUFU, 1 op) and sigmoid built on it
__device__ __forceinline__ float tanh_hw(float x) {
    float y;
    asm("tanh.approx.f32 %0, %1;" : "=f"(y) : "f"(x));
    return y;
}
__device__ __forceinline__ float sigmoid_hw(float x) {
    return fmaf(tanh_hw(0.5f * x), 0.5f, 0.5f);
}

__device__ __forceinline__ float sigmoid_x(float x) {   // exact-ish, for xg path unused
    return __fdividef(1.0f, 1.0f + __expf(-x));
}

// ---------------------------------------------------------------------------
// Kernel 1: xg[bt][n] = sum_f x[bt][f] * W_ih[n][f] + b_ih[n] + b_hh[n]
// Block (0,0) additionally repacks W_hh into g_Wq (consumed by the NEXT kernel).
// ---------------------------------------------------------------------------
__global__ __launch_bounds__(256) void xg_kernel(const float* __restrict__ x,
                                                 const float* __restrict__ Wih,
                                                 const float* __restrict__ Whh,
                                                 const float* __restrict__ b_ih,
                                                 const float* __restrict__ b_hh) {
    __shared__ float As[64][66];
    __shared__ float Bs[64][66];

    const int bt0 = blockIdx.x * 64;
    const int n0  = blockIdx.y * 64;
    const int tid = threadIdx.x;

    if (blockIdx.x == 0 && blockIdx.y == 0) {
#pragma unroll
        for (int p = 0; p < 2; p++) {
            int row = tid + p * 256;
            const float4* src = (const float4*)(Whh + (size_t)row * HID);
#pragma unroll
            for (int k4 = 0; k4 < 32; k4++)
                g_Wq[k4 * GATES + row] = src[k4];
        }
    }

    const float4* Ag = (const float4*)(x   + (size_t)bt0 * NFEAT);
    const float4* Bg = (const float4*)(Wih + (size_t)n0  * NFEAT);
#pragma unroll
    for (int p = 0; p < 4; p++) {
        int v = tid + p * 256;
        int m = v >> 4;
        int k = (v & 15) * 4;
        float4 qa = Ag[v];
        As[m][k] = qa.x; As[m][k+1] = qa.y; As[m][k+2] = qa.z; As[m][k+3] = qa.w;
        float4 qb = Bg[v];
        Bs[m][k] = qb.x; Bs[m][k+1] = qb.y; Bs[m][k+2] = qb.z; Bs[m][k+3] = qb.w;
    }
    __syncthreads();

    const int tx = tid & 31;
    const int ty = tid >> 5;

    unsigned long long acc[8][2];
#pragma unroll
    for (int i = 0; i < 8; i++)
#pragma unroll
        for (int j = 0; j < 2; j++) acc[i][j] = 0ULL;

#pragma unroll
    for (int k2 = 0; k2 < 32; k2++) {
        unsigned long long a2[8], b2[2];
#pragma unroll
        for (int i = 0; i < 8; i++)
            a2[i] = *(const unsigned long long*)&As[ty + i * 8][k2 * 2];
#pragma unroll
        for (int j = 0; j < 2; j++)
            b2[j] = *(const unsigned long long*)&Bs[tx + j * 32][k2 * 2];
#pragma unroll
        for (int i = 0; i < 8; i++)
#pragma unroll
            for (int j = 0; j < 2; j++)
                ffma2(acc[i][j], a2[i], b2[j]);
    }

    float bias[2];
#pragma unroll
    for (int j = 0; j < 2; j++) {
        int n = n0 + tx + j * 32;
        bias[j] = __ldg(&b_ih[n]) + __ldg(&b_hh[n]);
    }

#pragma unroll
    for (int i = 0; i < 8; i++) {
        int m = bt0 + ty + i * 8;
#pragma unroll
        for (int j = 0; j < 2; j++) {
            int n = n0 + tx + j * 32;
            g_xg[(size_t)m * GATES + n] = hsum2(acc[i][j]) + bias[j];
        }
    }
}

// ---------------------------------------------------------------------------
// Kernel 2: persistent LSTM. Coalesced warp tiling (warp = 4 row-pairs x 8 j);
// thread (rg,j) owns 2 rows x 4 gates, fully fused (one barrier/step).
// Weights: k4 0..26 smem; k4 27..31 streamed from L2 via depth-1 rolling
// VOLATILE loads (no register residency -> no spills; target regs <= ~100).
// Nonlinearities: HW tanh.approx (MUFU).
// ---------------------------------------------------------------------------
extern __shared__ char smem_raw[];

__global__ __launch_bounds__(LTHREADS, 1) void lstm_kernel(
        const float* __restrict__ W_out,
        const float* __restrict__ b_out,
        float* __restrict__ out) {

    // smem carve: weights (27*8192 = 221184B) | h double buffer (2*8*132*4 = 8448B)
    ulonglong2* w4s = (ulonglong2*)smem_raw;                        // [SMEM_K4][512]
    float* hbuf = (float*)(smem_raw + SMEM_K4 * GATES * 16);        // [2][8][HSTRIDE]

    const int tid  = threadIdx.x;
    const int b0   = blockIdx.x * BR;
    const int lane = tid & 31;
    const int warp = tid >> 5;
    const int rg   = lane >> 3;              // row-pair 0..3 -> rows 2rg, 2rg+1
    const int j    = warp * 8 + (lane & 7);  // output/hidden index 0..127

    const ulonglong2* __restrict__ Wg = (const ulonglong2*)g_Wq;

    // Prologue: smem weights (k4 0..26), zero h buffers
#pragma unroll
    for (int p = 0; p < SMEM_K4; p++) {
        int idx = tid + p * LTHREADS;
        w4s[idx] = Wg[idx];
    }
    for (int i = tid; i < 2 * BR * HSTRIDE; i += LTHREADS) hbuf[i] = 0.0f;
    __syncthreads();

    // Loop-invariant streamed-weight base pointers (one per gate)
    const ulonglong2* wp0 = &Wg[(size_t)SMEM_K4 * GATES + 0 * HID + j];
    const ulonglong2* wp1 = &Wg[(size_t)SMEM_K4 * GATES + 1 * HID + j];
    const ulonglong2* wp2 = &Wg[(size_t)SMEM_K4 * GATES + 2 * HID + j];
    const ulonglong2* wp3 = &Wg[(size_t)SMEM_K4 * GATES + 3 * HID + j];

    float cst[2] = {0.0f, 0.0f};

    for (int t = 0; t < SEQ; t++) {
        const int rb = t & 1;
        const float* __restrict__ hr = hbuf + rb * (BR * HSTRIDE);
        float*       __restrict__ hw = hbuf + (rb ^ 1) * (BR * HSTRIDE);

        // Prefetch first streamed batch (latency hidden under smem section)
        ulonglong2 wnext[4];
        wnext[0] = ldg_w(wp0); wnext[1] = ldg_w(wp1);
        wnext[2] = ldg_w(wp2); wnext[3] = ldg_w(wp3);

        // Prefetch this step's xg (DRAM; consumed at step end)
        float xg_v[2][4];
#pragma unroll
        for (int p = 0; p < 2; p++) {
            size_t base = ((size_t)((b0 + 2 * rg + p) * SEQ + t)) * GATES + j;
#pragma unroll
            for (int g = 0; g < 4; g++)
                xg_v[p][g] = __ldg(&g_xg[base + g * HID]);
        }

        unsigned long long acc[2][4];
#pragma unroll
        for (int p = 0; p < 2; p++)
#pragma unroll
            for (int g = 0; g < 4; g++) acc[p][g] = 0ULL;

        // -- smem weight section: k4 0..26 --
#pragma unroll 9
        for (int k4 = 0; k4 < SMEM_K4; k4++) {
            ulonglong2 h0 = *(const ulonglong2*)&hr[(2 * rg)     * HSTRIDE + k4 * 4];
            ulonglong2 h1 = *(const ulonglong2*)&hr[(2 * rg + 1) * HSTRIDE + k4 * 4];
#pragma unroll
            for (int g = 0; g < 4; g++) {
                ulonglong2 w = w4s[k4 * GATES + g * HID + j];
                ffma2(acc[0][g], h0.x, w.x);
                ffma2(acc[0][g], h0.y, w.y);
                ffma2(acc[1][g], h1.x, w.x);
                ffma2(acc[1][g], h1.y, w.y);
            }
        }

        // -- streamed weight section: k4 27..31, depth-1 rolling volatile loads --
#pragma unroll
        for (int s = 0; s < STR_K4; s++) {
            int k4 = SMEM_K4 + s;
            ulonglong2 wc[4];
#pragma unroll
            for (int g = 0; g < 4; g++) wc[g] = wnext[g];
            if (s < STR_K4 - 1) {
                size_t off = (size_t)(s + 1) * GATES;
                wnext[0] = ldg_w(wp0 + off); wnext[1] = ldg_w(wp1 + off);
                wnext[2] = ldg_w(wp2 + off); wnext[3] = ldg_w(wp3 + off);
            }
            ulonglong2 h0 = *(const ulonglong2*)&hr[(2 * rg)     * HSTRIDE + k4 * 4];
            ulonglong2 h1 = *(const ulonglong2*)&hr[(2 * rg + 1) * HSTRIDE + k4 * 4];
#pragma unroll
            for (int g = 0; g < 4; g++) {
                ffma2(acc[0][g], h0.x, wc[g].x);
                ffma2(acc[0][g], h0.y, wc[g].y);
                ffma2(acc[1][g], h1.x, wc[g].x);
                ffma2(acc[1][g], h1.y, wc[g].y);
            }
        }

        // -- Fused nonlinearity + state update (MUFU tanh) --
#pragma unroll
        for (int p = 0; p < 2; p++) {
            float gi = hsum2(acc[p][0]) + xg_v[p][0];
            float gf = hsum2(acc[p][1]) + xg_v[p][1];
            float gg = hsum2(acc[p][2]) + xg_v[p][2];
            float go = hsum2(acc[p][3]) + xg_v[p][3];
            float iv = sigmoid_hw(gi);
            float fv = sigmoid_hw(gf);
            float gv = tanh_hw(gg);
            float ov = sigmoid_hw(go);
            float cc = fv * cst[p] + iv * gv;
            cst[p] = cc;
            hw[(2 * rg + p) * HSTRIDE + j] = ov * tanh_hw(cc);
        }
        __syncthreads();   // single barrier: hw visible; hr free next step
    }

    // Final h: t=511 wrote buffer 0
    const float* hf = hbuf;   // [8][HSTRIDE]

    // -- Output projection: out[b][o] = h[b] . W_out[o] + b_out[o] --
#pragma unroll
    for (int p = 0; p < 2; p++) {
        int idx = tid + p * LTHREADS;      // 0..1023 -> (r, o)
        int r = idx >> 7;
        int o = idx & 127;
        const float4* wo  = (const float4*)(W_out + (size_t)o * HID);
        const float4* hrr = (const float4*)&hf[r * HSTRIDE];
        float s = __ldg(&b_out[o]);
#pragma unroll
        for (int k4 = 0; k4 < 32; k4++) {
            float4 w = wo[k4];
            float4 h = hrr[k4];
            s += w.x * h.x + w.y * h.y + w.z * h.z + w.w * h.w;
        }
        out[(size_t)(b0 + r) * NOUT + o] = s;
    }
}

// ---------------------------------------------------------------------------
// Launch (2 kernels)
// ---------------------------------------------------------------------------
extern "C" void kernel_launch(void* const* d_in, const int* in_sizes, int n_in,
                              void* d_out, int out_size) {
    const float* x     = (const float*)d_in[0];
    const float* W_ih  = (const float*)d_in[1];
    const float* W_hh  = (const float*)d_in[2];
    const float* b_ih  = (const float*)d_in[3];
    const float* b_hh  = (const float*)d_in[4];
    const float* W_out = (const float*)d_in[5];
    const float* b_out = (const float*)d_in[6];
    float* out = (float*)d_out;

    const int lstm_smem = SMEM_K4 * GATES * 16 + 2 * BR * HSTRIDE * 4; // 221184 + 8448
    cudaFuncSetAttribute(lstm_kernel,
                         cudaFuncAttributeMaxDynamicSharedMemorySize, lstm_smem);

    dim3 grid1((BATCH * SEQ) / 64, GATES / 64);
    xg_kernel<<<grid1, 256>>>(x, W_ih, W_hh, b_ih, b_hh);

    lstm_kernel<<<NCTA, LTHREADS, lstm_smem>>>(W_out, b_out, out);
}